// round 8
// baseline (speedup 1.0000x reference)
#include <cuda_runtime.h>
#include <cuda_fp16.h>
#include <math.h>

#define GX 128
#define GY 128
#define GZ 128
#define VDIM 28
#define NUM_RAYS 8192
#define NUM_SAMPLES 128
#define NVOX (GX*GY*GZ)
#define NSAMP (NUM_RAYS*NUM_SAMPLES)

#define NCHUNK 16                     // x-chunks of 8 planes each
#define CHUNK_VOX (NVOX/NCHUNK)       // 131072
#define RBLK (CHUNK_VOX/256)          // 512 reduce blocks / chunk
#define RB 280                        // render blocks / chunk (capacity)
#define CAP (RB*256)                  // 71680 records (expected 65536, ~16 sigma)

struct __align__(16) Rec { unsigned int idx, out, xy, zdd; };

// [x][y][z] pair layout: entry v = fp16 (sigma,r,g,b) of voxel v and v+1 (+z).
__device__ uint4  g_pairs[NVOX];
__device__ Rec    g_bins[(size_t)NCHUNK * CAP];
__device__ int    g_cnt[NCHUNK];
__device__ int    g_done;             // completed reduce blocks (global)
__device__ float4 g_rec2[NSAMP];      // per-sample (att, r, g, b)

// ---------------------------------------------------------------------------
__device__ __forceinline__ void sh_basis9(const float* __restrict__ ang, float* b) {
    float theta = ang[0], phi = ang[1];
    float st, ct, sp, cp;
    __sincosf(theta, &st, &ct);
    __sincosf(phi, &sp, &cp);
    const float y00 = 0.28209479177387814f;
    const float h3  = 0.4886025119029199f;
    const float q5  = 0.31539156525252005f;
    const float h15 = 1.0925484305920792f;
    const float q15 = 0.5462742152960396f;
    b[0] = y00;
    b[1] = h3 * st * sp;
    b[2] = h3 * ct;
    b[3] = h3 * st * cp;
    b[4] = h15 * st * cp * st * sp;
    b[5] = h15 * st * sp * ct;
    b[6] = q5 * (3.0f * ct * ct - 1.0f);
    b[7] = h15 * st * cp * ct;
    b[8] = q15 * ((st * cp) * (st * cp) - (st * sp) * (st * sp));
}

__device__ __forceinline__ uint2 contract_voxel(const float* __restrict__ grid,
                                                const float* __restrict__ b, int v) {
    const float4* vp = (const float4*)(grid + (size_t)v * VDIM);
    float f[VDIM];
    #pragma unroll
    for (int i = 0; i < 7; i++) {
        float4 t = __ldcs(vp + i);     // evict-first stream (NOT .cv — R7 lesson)
        f[i*4+0] = t.x; f[i*4+1] = t.y; f[i*4+2] = t.z; f[i*4+3] = t.w;
    }
    float r = 0.f, g = 0.f, bl = 0.f;
    #pragma unroll
    for (int k = 0; k < 9; k++) {
        r  = fmaf(f[1  + k], b[k], r);
        g  = fmaf(f[10 + k], b[k], g);
        bl = fmaf(f[19 + k], b[k], bl);
    }
    __half2 h0 = __floats2half2_rn(f[0], r);
    __half2 h1 = __floats2half2_rn(g, bl);
    uint2 u;
    u.x = *(const unsigned int*)&h0;
    u.y = *(const unsigned int*)&h1;
    return u;
}

__device__ __forceinline__ float4 zlerp_pair(uint4 t, float zd) {
    float2 a0 = __half22float2(*(__half2*)&t.x);
    float2 a1 = __half22float2(*(__half2*)&t.y);
    float2 b0 = __half22float2(*(__half2*)&t.z);
    float2 b1 = __half22float2(*(__half2*)&t.w);
    return make_float4(fmaf(b0.x - a0.x, zd, a0.x),
                       fmaf(b0.y - a0.y, zd, a0.y),
                       fmaf(b1.x - a1.x, zd, a1.x),
                       fmaf(b1.y - a1.y, zd, a1.y));
}

__device__ __forceinline__ float4 f4lerp(float4 a, float4 b, float t) {
    return make_float4(fmaf(b.x - a.x, t, a.x),
                       fmaf(b.y - a.y, t, a.y),
                       fmaf(b.z - a.z, t, a.z),
                       fmaf(b.w - a.w, t, a.w));
}

// ---------------------------------------------------------------------------
__global__ void zero_kernel() {
    if (threadIdx.x < NCHUNK) g_cnt[threadIdx.x] = 0;
    if (threadIdx.x == 0) g_done = 0;
}

// ---------------------------------------------------------------------------
// Bin: 1024 samples/block, smem-staged scatter into 16 x-chunk bins.
// ---------------------------------------------------------------------------
__global__ __launch_bounds__(256) void bin_kernel(
    const float* __restrict__ pos, const float* __restrict__ dist)
{
    __shared__ int scnt[NCHUNK];
    __shared__ int sbase[NCHUNK];
    __shared__ int soff[NCHUNK];
    __shared__ Rec srec[1024];

    int t = threadIdx.x;
    if (t < NCHUNK) scnt[t] = 0;
    __syncthreads();

    int base = blockIdx.x * 1024;
    Rec r[4]; int ck[4]; int slot[4];
    #pragma unroll
    for (int k = 0; k < 4; k++) {
        int i = base + k*256 + t;
        const float* p = pos + (size_t)i * 3;
        float x = p[0], y = p[1], z = p[2];
        float d = dist[i];
        int xi = (int)x, yi = (int)y, zi = (int)z;   // in [0,125]
        __half2 hxy = __floats2half2_rn(x - (float)xi, y - (float)yi);
        __half2 hzd = __floats2half2_rn(z - (float)zi, d);
        r[k].idx = (xi << 14) | (yi << 7) | zi;
        r[k].out = (unsigned)i;
        r[k].xy  = *(unsigned int*)&hxy;
        r[k].zdd = *(unsigned int*)&hzd;
        ck[k] = xi >> 3;
        slot[k] = atomicAdd(&scnt[ck[k]], 1);
    }
    __syncthreads();
    if (t == 0) {
        int run = 0;
        #pragma unroll
        for (int c = 0; c < NCHUNK; c++) { soff[c] = run; run += scnt[c]; }
    }
    if (t < NCHUNK) sbase[t] = atomicAdd(&g_cnt[t], scnt[t]);
    __syncthreads();
    #pragma unroll
    for (int k = 0; k < 4; k++) srec[soff[ck[k]] + slot[k]] = r[k];
    __syncthreads();

    for (int k = t; k < 1024; k += 256) {
        int c = 0;
        #pragma unroll
        for (int j = 1; j < NCHUNK; j++) if (k >= soff[j]) c = j;
        int gpos = sbase[c] + (k - soff[c]);
        if (gpos < CAP) g_bins[(size_t)c * CAP + gpos] = srec[k];
    }
}

// ---------------------------------------------------------------------------
// Fused kernel: interleaved reduce + render blocks, one full-size launch.
// Superchunk sc: RBLK reduce blocks (chunk sc), then RB render blocks
// (chunk sc-2). Render chunk c spins until reduce chunks <= c+1 complete.
// ---------------------------------------------------------------------------
__global__ __launch_bounds__(256) void fused_kernel(
    const float* __restrict__ grid, const float* __restrict__ ang)
{
    __shared__ uint2 s[257];
    int t = threadIdx.x;

    // Decode superchunk + offset from blockIdx.
    int b = blockIdx.x, sc = 0;
    #pragma unroll 1
    for (;;) {
        int n = (sc < NCHUNK ? RBLK : 0) + (sc >= 2 ? RB : 0);
        if (b < n) break;
        b -= n; sc++;
    }

    if (sc < NCHUNK && b < RBLK) {
        // ---- reduce role: chunk sc, block b ----
        float bb[9];
        sh_basis9(ang, bb);
        int vbase = sc * CHUNK_VOX + b * 256;
        int v = vbase + t;
        s[t] = contract_voxel(grid, bb, v);
        if (t == 0) {
            int v2 = vbase + 256;
            if (v2 >= NVOX) v2 = NVOX - 1;   // clamped value never read
            s[256] = contract_voxel(grid, bb, v2);
        }
        __syncthreads();
        uint2 a = s[t], c = s[t + 1];
        g_pairs[v] = make_uint4(a.x, a.y, c.x, c.y);
        __threadfence();
        __syncthreads();
        if (t == 0) atomicAdd(&g_done, 1);
    } else {
        // ---- render role: chunk sc-2 ----
        int c = sc - 2;
        int rb = b - (sc < NCHUNK ? RBLK : 0);
        int needc = c + 2; if (needc > NCHUNK) needc = NCHUNK;
        int need = RBLK * needc;
        if (t == 0) {
            int v;
            do {
                asm volatile("ld.global.acquire.gpu.b32 %0, [%1];"
                             : "=r"(v) : "l"(&g_done) : "memory");
            } while (v < need);
        }
        __syncthreads();

        int cnt = g_cnt[c]; if (cnt > CAP) cnt = CAP;
        int j = rb * 256 + t;
        if (j >= cnt) return;
        Rec r = g_bins[(size_t)c * CAP + j];
        float2 xy  = __half22float2(*(__half2*)&r.xy);
        float2 zdd = __half22float2(*(__half2*)&r.zdd);
        int e = (int)r.idx;
        const uint4* __restrict__ G = g_pairs;
        uint4 t00 = __ldcg(G + e);                   // (x0,y0)
        uint4 t01 = __ldcg(G + e + 128);             // (x0,y1)
        uint4 t10 = __ldcg(G + e + 16384);           // (x1,y0)
        uint4 t11 = __ldcg(G + e + 16384 + 128);     // (x1,y1)
        float4 v00 = zlerp_pair(t00, zdd.x);
        float4 v01 = zlerp_pair(t01, zdd.x);
        float4 v10 = zlerp_pair(t10, zdd.x);
        float4 v11 = zlerp_pair(t11, zdd.x);
        float4 v0 = f4lerp(v00, v10, xy.x);
        float4 v1 = f4lerp(v01, v11, xy.x);
        float4 v  = f4lerp(v0, v1, xy.y);
        float att = __expf(-v.x * zdd.y);
        g_rec2[r.out] = make_float4(att, v.y, v.z, v.w);
    }
}

// ---------------------------------------------------------------------------
// Finalize: per-ray scan of att, weight, rgb sum. 128 threads = 1 ray.
// ---------------------------------------------------------------------------
__global__ __launch_bounds__(128) void finalize_kernel(float* __restrict__ out) {
    __shared__ float wsum[4];
    __shared__ float acc[4][3];
    int ray = blockIdx.x;
    int t = threadIdx.x, wid = t >> 5, lane = t & 31;

    float4 rec = g_rec2[ray * NUM_SAMPLES + t];
    float att = rec.x;
    float inc = att;
    #pragma unroll
    for (int o = 1; o < 32; o <<= 1) {
        float n = __shfl_up_sync(0xffffffffu, inc, o);
        if (lane >= o) inc += n;
    }
    if (lane == 31) wsum[wid] = inc;
    __syncthreads();
    float off = 0.f;
    #pragma unroll
    for (int w = 0; w < 3; w++) if (w < wid) off += wsum[w];
    float T = off + inc;

    float w = T * (1.0f - att);
    float ar = w * rec.y, ag = w * rec.z, ab = w * rec.w;
    #pragma unroll
    for (int o = 16; o > 0; o >>= 1) {
        ar += __shfl_xor_sync(0xffffffffu, ar, o);
        ag += __shfl_xor_sync(0xffffffffu, ag, o);
        ab += __shfl_xor_sync(0xffffffffu, ab, o);
    }
    if (lane == 0) { acc[wid][0] = ar; acc[wid][1] = ag; acc[wid][2] = ab; }
    __syncthreads();
    if (t < 3) out[ray * 3 + t] = acc[0][t] + acc[1][t] + acc[2][t] + acc[3][t];
}

extern "C" void kernel_launch(void* const* d_in, const int* in_sizes, int n_in,
                              void* d_out, int out_size) {
    const float* voxel_grid = (const float*)d_in[0];
    const float* sample_positions = (const float*)d_in[1];
    const float* sample_distances = (const float*)d_in[2];
    const float* viewing_angle = (const float*)d_in[3];
    float* out = (float*)d_out;

    zero_kernel<<<1, 32>>>();
    bin_kernel<<<NSAMP / 1024, 256>>>(sample_positions, sample_distances);

    int nblocks = NCHUNK * RBLK + NCHUNK * RB;   // 8192 + 4480 = 12672
    fused_kernel<<<nblocks, 256>>>(voxel_grid, viewing_angle);

    finalize_kernel<<<NUM_RAYS, 128>>>(out);
}

// round 9
// speedup vs baseline: 1.8466x; 1.8466x over previous
#include <cuda_runtime.h>
#include <cuda_fp16.h>
#include <math.h>

#define GX 128
#define GY 128
#define GZ 128
#define VDIM 28
#define NUM_RAYS 8192
#define NUM_SAMPLES 128
#define NVOX (GX*GY*GZ)

// Reduced grid: 8 B per voxel, fp16 (sigma, r | g, b), [x][y][z] layout.
// 16 MB total -> half of R4's grid; render's compulsory DRAM fetch halves.
__device__ uint2 g_vox[NVOX];

// ---------------------------------------------------------------------------
// SH basis (degree 2), reference coefficient order.
// ---------------------------------------------------------------------------
__device__ __forceinline__ void sh_basis9(const float* __restrict__ ang, float* b) {
    float theta = ang[0], phi = ang[1];
    float st, ct, sp, cp;
    __sincosf(theta, &st, &ct);
    __sincosf(phi, &sp, &cp);
    const float y00 = 0.28209479177387814f;
    const float h3  = 0.4886025119029199f;
    const float q5  = 0.31539156525252005f;
    const float h15 = 1.0925484305920792f;
    const float q15 = 0.5462742152960396f;
    b[0] = y00;
    b[1] = h3 * st * sp;
    b[2] = h3 * ct;
    b[3] = h3 * st * cp;
    b[4] = h15 * st * cp * st * sp;
    b[5] = h15 * st * sp * ct;
    b[6] = q5 * (3.0f * ct * ct - 1.0f);
    b[7] = h15 * st * cp * ct;
    b[8] = q15 * ((st * cp) * (st * cp) - (st * sp) * (st * sp));
}

// ---------------------------------------------------------------------------
// Kernel 1: contract 28 features -> 8 B fp16 voxel. Pure streaming, no smem.
// 235 MB read (__ldcs evict-first) + 16 MB write.
// ---------------------------------------------------------------------------
__global__ __launch_bounds__(256) void reduce_kernel(
    const float* __restrict__ grid, const float* __restrict__ ang)
{
    int v = blockIdx.x * 256 + threadIdx.x;
    float b[9];
    sh_basis9(ang, b);

    const float4* vp = (const float4*)(grid + (size_t)v * VDIM);
    float f[VDIM];
    #pragma unroll
    for (int i = 0; i < 7; i++) {
        float4 t = __ldcs(vp + i);
        f[i*4+0] = t.x; f[i*4+1] = t.y; f[i*4+2] = t.z; f[i*4+3] = t.w;
    }
    float r = 0.f, g = 0.f, bl = 0.f;
    #pragma unroll
    for (int k = 0; k < 9; k++) {
        r  = fmaf(f[1  + k], b[k], r);
        g  = fmaf(f[10 + k], b[k], g);
        bl = fmaf(f[19 + k], b[k], bl);
    }
    __half2 h0 = __floats2half2_rn(f[0], r);
    __half2 h1 = __floats2half2_rn(g, bl);
    uint2 u;
    u.x = *(const unsigned int*)&h0;
    u.y = *(const unsigned int*)&h1;
    g_vox[v] = u;
}

// ---------------------------------------------------------------------------
// Kernel 2: rendering, one sample per thread. 8 x uint2 gathers per sample.
// 128 threads (4 warps) per ray, 2 rays per 256-thread block.
// ---------------------------------------------------------------------------
__device__ __forceinline__ float4 unpack8(uint2 u) {
    float2 a = __half22float2(*(__half2*)&u.x);   // sigma, r
    float2 b = __half22float2(*(__half2*)&u.y);   // g, b
    return make_float4(a.x, a.y, b.x, b.y);
}

__device__ __forceinline__ float4 f4lerp(float4 a, float4 b, float t) {
    return make_float4(fmaf(b.x - a.x, t, a.x),
                       fmaf(b.y - a.y, t, a.y),
                       fmaf(b.z - a.z, t, a.z),
                       fmaf(b.w - a.w, t, a.w));
}

__device__ __forceinline__ float4 trilerp(float x, float y, float z) {
    int xi = (int)x, yi = (int)y, zi = (int)z;   // positions in [0, 126]
    float xd = x - (float)xi, yd = y - (float)yi, zd = z - (float)zi;
    int i = (xi << 14) + (yi << 7) + zi;
    const uint2* __restrict__ G = g_vox;
    // Issue all 8 loads up front for max MLP.
    uint2 u000 = __ldcg(G + i);
    uint2 u001 = __ldcg(G + i + 1);
    uint2 u010 = __ldcg(G + i + GZ);
    uint2 u011 = __ldcg(G + i + GZ + 1);
    uint2 u100 = __ldcg(G + i + GY*GZ);
    uint2 u101 = __ldcg(G + i + GY*GZ + 1);
    uint2 u110 = __ldcg(G + i + GY*GZ + GZ);
    uint2 u111 = __ldcg(G + i + GY*GZ + GZ + 1);
    float4 c000 = unpack8(u000), c001 = unpack8(u001);
    float4 c010 = unpack8(u010), c011 = unpack8(u011);
    float4 c100 = unpack8(u100), c101 = unpack8(u101);
    float4 c110 = unpack8(u110), c111 = unpack8(u111);
    float4 c00 = f4lerp(c000, c100, xd);
    float4 c01 = f4lerp(c001, c101, xd);
    float4 c10 = f4lerp(c010, c110, xd);
    float4 c11 = f4lerp(c011, c111, xd);
    float4 c0 = f4lerp(c00, c10, yd);
    float4 c1 = f4lerp(c01, c11, yd);
    return f4lerp(c0, c1, zd);
}

__global__ __launch_bounds__(256) void render_kernel(
    const float* __restrict__ pos, const float* __restrict__ dist,
    float* __restrict__ out)
{
    __shared__ float s_wsum[8];      // per-warp att totals
    __shared__ float s_acc[8][3];    // per-warp rgb partials

    int tid  = threadIdx.x;
    int wid  = tid >> 5;             // warp in block: 0..7
    int lane = tid & 31;
    int wir  = wid & 3;              // warp within ray: 0..3
    int rbase = wid & 4;             // first warp index of this thread's ray
    int ray  = blockIdx.x * 2 + (tid >> 7);
    int s    = tid & 127;            // sample index within ray

    const float* p = pos + (size_t)ray * (NUM_SAMPLES * 3) + s * 3;
    float px = p[0], py = p[1], pz = p[2];
    float d  = dist[(size_t)ray * NUM_SAMPLES + s];

    float4 sm = trilerp(px, py, pz);
    float att = __expf(-sm.x * d);

    // Inclusive scan of att over the ray's 128 samples.
    float inc = att;
    #pragma unroll
    for (int o = 1; o < 32; o <<= 1) {
        float n = __shfl_up_sync(0xffffffffu, inc, o);
        if (lane >= o) inc += n;
    }
    if (lane == 31) s_wsum[wid] = inc;
    __syncthreads();
    float off = 0.f;
    #pragma unroll
    for (int w = 0; w < 3; w++)
        if (w < wir) off += s_wsum[rbase + w];
    float T = inc + off;

    float w = T * (1.0f - att);
    float ar = w * sm.y, ag = w * sm.z, ab = w * sm.w;

    #pragma unroll
    for (int o = 16; o > 0; o >>= 1) {
        ar += __shfl_xor_sync(0xffffffffu, ar, o);
        ag += __shfl_xor_sync(0xffffffffu, ag, o);
        ab += __shfl_xor_sync(0xffffffffu, ab, o);
    }
    if (lane == 0) {
        s_acc[wid][0] = ar;
        s_acc[wid][1] = ag;
        s_acc[wid][2] = ab;
    }
    __syncthreads();
    if (wir == 0 && lane < 3) {
        float v = s_acc[rbase + 0][lane] + s_acc[rbase + 1][lane]
                + s_acc[rbase + 2][lane] + s_acc[rbase + 3][lane];
        out[ray * 3 + lane] = v;
    }
}

extern "C" void kernel_launch(void* const* d_in, const int* in_sizes, int n_in,
                              void* d_out, int out_size) {
    const float* voxel_grid = (const float*)d_in[0];
    const float* sample_positions = (const float*)d_in[1];
    const float* sample_distances = (const float*)d_in[2];
    const float* viewing_angle = (const float*)d_in[3];
    float* out = (float*)d_out;

    reduce_kernel<<<NVOX / 256, 256>>>(voxel_grid, viewing_angle);
    render_kernel<<<NUM_RAYS / 2, 256>>>(sample_positions, sample_distances, out);
}

// round 10
// speedup vs baseline: 2.0402x; 1.1049x over previous
#include <cuda_runtime.h>
#include <cuda_fp16.h>
#include <math.h>

#define GX 128
#define GY 128
#define GZ 128
#define VDIM 28
#define NUM_RAYS 8192
#define NUM_SAMPLES 128
#define NVOX (GX*GY*GZ)

// Paired reduced grid ([x][y][z] layout): entry v holds fp16 (sigma,r,g,b) for
// voxel v AND voxel v+1 (+z). One aligned uint4 load = both z-corners.
// 32 MB; kept L2-resident via evict_last cache-policy hints on store + load.
__device__ uint4 g_pairs[NVOX];

// ---------------------------------------------------------------------------
// L2 evict_last policy helpers (persistence without accessPolicyWindow).
// ---------------------------------------------------------------------------
__device__ __forceinline__ unsigned long long evict_last_policy() {
    unsigned long long p;
    asm("createpolicy.fractional.L2::evict_last.b64 %0, 1.0;" : "=l"(p));
    return p;
}
__device__ __forceinline__ void st_el(uint4* addr, uint4 v, unsigned long long pol) {
    asm volatile("st.global.L2::cache_hint.v4.u32 [%0], {%1,%2,%3,%4}, %5;"
                 :: "l"(addr), "r"(v.x), "r"(v.y), "r"(v.z), "r"(v.w), "l"(pol)
                 : "memory");
}
__device__ __forceinline__ uint4 ld_el(const uint4* addr, unsigned long long pol) {
    uint4 v;
    asm volatile("ld.global.nc.L2::cache_hint.v4.u32 {%0,%1,%2,%3}, [%4], %5;"
                 : "=r"(v.x), "=r"(v.y), "=r"(v.z), "=r"(v.w)
                 : "l"(addr), "l"(pol));
    return v;
}

// ---------------------------------------------------------------------------
// SH basis (degree 2), reference coefficient order.
// ---------------------------------------------------------------------------
__device__ __forceinline__ void sh_basis9(const float* __restrict__ ang, float* b) {
    float theta = ang[0], phi = ang[1];
    float st, ct, sp, cp;
    __sincosf(theta, &st, &ct);
    __sincosf(phi, &sp, &cp);
    const float y00 = 0.28209479177387814f;
    const float h3  = 0.4886025119029199f;
    const float q5  = 0.31539156525252005f;
    const float h15 = 1.0925484305920792f;
    const float q15 = 0.5462742152960396f;
    b[0] = y00;
    b[1] = h3 * st * sp;
    b[2] = h3 * ct;
    b[3] = h3 * st * cp;
    b[4] = h15 * st * cp * st * sp;
    b[5] = h15 * st * sp * ct;
    b[6] = q5 * (3.0f * ct * ct - 1.0f);
    b[7] = h15 * st * cp * ct;
    b[8] = q15 * ((st * cp) * (st * cp) - (st * sp) * (st * sp));
}

// Contract 28 features of voxel v -> packed fp16 (sigma,r | g,b).
// Raw grid reads: __ldcs (evict_first) so the stream evicts itself, not g_pairs.
__device__ __forceinline__ uint2 contract_voxel(const float* __restrict__ grid,
                                                const float* __restrict__ b, int v) {
    const float4* vp = (const float4*)(grid + (size_t)v * VDIM);
    float f[VDIM];
    #pragma unroll
    for (int i = 0; i < 7; i++) {
        float4 t = __ldcs(vp + i);
        f[i*4+0] = t.x; f[i*4+1] = t.y; f[i*4+2] = t.z; f[i*4+3] = t.w;
    }
    float r = 0.f, g = 0.f, bl = 0.f;
    #pragma unroll
    for (int k = 0; k < 9; k++) {
        r  = fmaf(f[1  + k], b[k], r);
        g  = fmaf(f[10 + k], b[k], g);
        bl = fmaf(f[19 + k], b[k], bl);
    }
    __half2 h0 = __floats2half2_rn(f[0], r);
    __half2 h1 = __floats2half2_rn(g, bl);
    uint2 u;
    u.x = *(const unsigned int*)&h0;
    u.y = *(const unsigned int*)&h1;
    return u;
}

// ---------------------------------------------------------------------------
// Kernel 1: contract + pack with +z neighbor; store with evict_last hint.
// ---------------------------------------------------------------------------
__global__ __launch_bounds__(256) void reduce_kernel(
    const float* __restrict__ grid, const float* __restrict__ ang)
{
    __shared__ uint2 s[257];
    float b[9];
    sh_basis9(ang, b);

    int base = blockIdx.x * 256;
    int t = threadIdx.x;
    int v = base + t;
    s[t] = contract_voxel(grid, b, v);
    if (t == 0) {
        int v2 = base + 256;
        if (v2 >= NVOX) v2 = NVOX - 1;   // value never read; keep in-bounds
        s[256] = contract_voxel(grid, b, v2);
    }
    __syncthreads();
    uint2 a = s[t], c = s[t + 1];
    st_el(&g_pairs[v], make_uint4(a.x, a.y, c.x, c.y), evict_last_policy());
}

// ---------------------------------------------------------------------------
// Kernel 2: rendering, one sample per thread. 4 evict_last uint4 gathers.
// 128 threads (4 warps) per ray, 2 rays per 256-thread block.
// ---------------------------------------------------------------------------
__device__ __forceinline__ float4 zlerp_pair(uint4 t, float zd) {
    float2 a0 = __half22float2(*(__half2*)&t.x);
    float2 a1 = __half22float2(*(__half2*)&t.y);
    float2 b0 = __half22float2(*(__half2*)&t.z);
    float2 b1 = __half22float2(*(__half2*)&t.w);
    return make_float4(fmaf(b0.x - a0.x, zd, a0.x),
                       fmaf(b0.y - a0.y, zd, a0.y),
                       fmaf(b1.x - a1.x, zd, a1.x),
                       fmaf(b1.y - a1.y, zd, a1.y));
}

__device__ __forceinline__ float4 f4lerp(float4 a, float4 b, float t) {
    return make_float4(fmaf(b.x - a.x, t, a.x),
                       fmaf(b.y - a.y, t, a.y),
                       fmaf(b.z - a.z, t, a.z),
                       fmaf(b.w - a.w, t, a.w));
}

__device__ __forceinline__ float4 trilerp(float x, float y, float z,
                                          unsigned long long pol) {
    int xi = (int)x, yi = (int)y, zi = (int)z;   // positions in [0, 126]
    float xd = x - (float)xi, yd = y - (float)yi, zd = z - (float)zi;
    int i = (xi << 14) + (yi << 7) + zi;
    const uint4* __restrict__ G = g_pairs;
    uint4 t00 = ld_el(G + i, pol);                 // (x0,y0)
    uint4 t01 = ld_el(G + i + GZ, pol);            // (x0,y1)
    uint4 t10 = ld_el(G + i + GY*GZ, pol);         // (x1,y0)
    uint4 t11 = ld_el(G + i + GY*GZ + GZ, pol);    // (x1,y1)
    float4 v00 = zlerp_pair(t00, zd);
    float4 v01 = zlerp_pair(t01, zd);
    float4 v10 = zlerp_pair(t10, zd);
    float4 v11 = zlerp_pair(t11, zd);
    float4 v0 = f4lerp(v00, v10, xd);
    float4 v1 = f4lerp(v01, v11, xd);
    return f4lerp(v0, v1, yd);
}

__global__ __launch_bounds__(256) void render_kernel(
    const float* __restrict__ pos, const float* __restrict__ dist,
    float* __restrict__ out)
{
    __shared__ float s_wsum[8];      // per-warp att totals
    __shared__ float s_acc[8][3];    // per-warp rgb partials

    int tid  = threadIdx.x;
    int wid  = tid >> 5;             // warp in block: 0..7
    int lane = tid & 31;
    int wir  = wid & 3;              // warp within ray: 0..3
    int rbase = wid & 4;             // first warp index of this thread's ray
    int ray  = blockIdx.x * 2 + (tid >> 7);
    int s    = tid & 127;            // sample index within ray

    unsigned long long pol = evict_last_policy();

    const float* p = pos + (size_t)ray * (NUM_SAMPLES * 3) + s * 3;
    float px = p[0], py = p[1], pz = p[2];
    float d  = dist[(size_t)ray * NUM_SAMPLES + s];

    float4 sm = trilerp(px, py, pz, pol);
    float att = __expf(-sm.x * d);

    // Inclusive scan of att over the ray's 128 samples.
    float inc = att;
    #pragma unroll
    for (int o = 1; o < 32; o <<= 1) {
        float n = __shfl_up_sync(0xffffffffu, inc, o);
        if (lane >= o) inc += n;
    }
    if (lane == 31) s_wsum[wid] = inc;
    __syncthreads();
    float off = 0.f;
    #pragma unroll
    for (int w = 0; w < 3; w++)
        if (w < wir) off += s_wsum[rbase + w];
    float T = inc + off;

    float w = T * (1.0f - att);
    float ar = w * sm.y, ag = w * sm.z, ab = w * sm.w;

    #pragma unroll
    for (int o = 16; o > 0; o >>= 1) {
        ar += __shfl_xor_sync(0xffffffffu, ar, o);
        ag += __shfl_xor_sync(0xffffffffu, ag, o);
        ab += __shfl_xor_sync(0xffffffffu, ab, o);
    }
    if (lane == 0) {
        s_acc[wid][0] = ar;
        s_acc[wid][1] = ag;
        s_acc[wid][2] = ab;
    }
    __syncthreads();
    if (wir == 0 && lane < 3) {
        float v = s_acc[rbase + 0][lane] + s_acc[rbase + 1][lane]
                + s_acc[rbase + 2][lane] + s_acc[rbase + 3][lane];
        out[ray * 3 + lane] = v;
    }
}

extern "C" void kernel_launch(void* const* d_in, const int* in_sizes, int n_in,
                              void* d_out, int out_size) {
    const float* voxel_grid = (const float*)d_in[0];
    const float* sample_positions = (const float*)d_in[1];
    const float* sample_distances = (const float*)d_in[2];
    const float* viewing_angle = (const float*)d_in[3];
    float* out = (float*)d_out;

    reduce_kernel<<<NVOX / 256, 256>>>(voxel_grid, viewing_angle);
    render_kernel<<<NUM_RAYS / 2, 256>>>(sample_positions, sample_distances, out);
}